// round 1
// baseline (speedup 1.0000x reference)
#include <cuda_runtime.h>
#include <cuda_bf16.h>
#include <math.h>

// ---------------- problem constants ----------------
#define B_ROWS   16384
#define D_DIM    1024
#define ORD_H    512
#define N_EXP    7
#define MAX_TILES 136                 // ceil(B/128) + up to 7 expert partial tiles
#define MAX_SLOTS (MAX_TILES * 128)   // 17408 compact (padded) slots

// ---------------- static device scratch (no allocations allowed) ----------------
// float scratch laid out in one big buffer
#define OFF_HC  0LL
#define OFF_HR  (OFF_HC + (long long)B_ROWS * D_DIM)        // 16,777,216
#define OFF_DF  (OFF_HR + (long long)B_ROWS * D_DIM)
#define OFF_HO  (OFF_DF + (long long)B_ROWS * D_DIM)
#define OFF_H1  (OFF_HO + (long long)B_ROWS * ORD_H)
#define OFF_H2  (OFF_H1 + (long long)MAX_SLOTS * D_DIM)
#define TOTAL_F (OFF_H2 + (long long)MAX_SLOTS * D_DIM)

__device__ float g_buf[TOTAL_F];

__device__ int d_size_idx[B_ROWS];
__device__ int d_perm[MAX_SLOTS];
__device__ int d_tile_expert[MAX_TILES];
__device__ int d_count[N_EXP];
__device__ int d_cursor[N_EXP];
__device__ int d_off[N_EXP];

// ---------------- tiled fp32 SGEMM: C = relu(A @ W + bias) ----------------
// A: [M,K] row-major (optionally gathered through d_perm), W: [K,N], C: [Mtiles*128, N]
// If useExpert: per-M-tile expert id from d_tile_expert selects W/bias slice.
#define BM 128
#define BN 128
#define BK 8
#define TM 8
#define TN 8

__global__ __launch_bounds__(256)
void sgemm_relu(const float* __restrict__ A,
                const float* __restrict__ Wb,
                const float* __restrict__ bb,
                float* __restrict__ C,
                int K, int N,
                int useExpert, int gatherA,
                long long wStride, int bStride)
{
    const int tileM = blockIdx.x;
    const int tileN = blockIdx.y;

    int e = 0;
    if (useExpert) {
        e = d_tile_expert[tileM];
        if (e < 0) return;
    }
    const float* W    = Wb + (long long)e * wStride;
    const float* bias = bb + (long long)e * bStride;

    __shared__ float As[BK][BM];
    __shared__ float Bs[BK][BN];

    const int tid  = threadIdx.x;
    const int tRow = tid >> 4;      // 0..15
    const int tCol = tid & 15;      // 0..15

    // A tile load mapping: 128 rows x 2 float4/row
    const int aRow  = tid >> 1;
    const int aCol4 = (tid & 1) * 4;
    // B tile load mapping: 8 rows x 32 float4/row
    const int bRow  = tid >> 5;
    const int bCol4 = (tid & 31) * 4;

    // resolve source row for A
    const int slot = tileM * BM + aRow;
    long long srcRow;
    if (useExpert && gatherA) srcRow = d_perm[slot];   // may be -1 (padding)
    else                      srcRow = slot;
    const float* Arow = (srcRow >= 0) ? (A + srcRow * (long long)K) : nullptr;

    float acc[TM][TN];
    #pragma unroll
    for (int i = 0; i < TM; i++)
        #pragma unroll
        for (int j = 0; j < TN; j++) acc[i][j] = 0.f;

    float regM[TM], regN[TN];

    for (int k0 = 0; k0 < K; k0 += BK) {
        float4 av = Arow ? *reinterpret_cast<const float4*>(Arow + k0 + aCol4)
                         : make_float4(0.f, 0.f, 0.f, 0.f);
        As[aCol4 + 0][aRow] = av.x;
        As[aCol4 + 1][aRow] = av.y;
        As[aCol4 + 2][aRow] = av.z;
        As[aCol4 + 3][aRow] = av.w;

        float4 bv = *reinterpret_cast<const float4*>(
            W + (long long)(k0 + bRow) * N + tileN * BN + bCol4);
        *reinterpret_cast<float4*>(&Bs[bRow][bCol4]) = bv;

        __syncthreads();
        #pragma unroll
        for (int kk = 0; kk < BK; kk++) {
            #pragma unroll
            for (int i = 0; i < TM; i++) regM[i] = As[kk][tRow * TM + i];
            #pragma unroll
            for (int j = 0; j < TN; j++) regN[j] = Bs[kk][tCol * TN + j];
            #pragma unroll
            for (int i = 0; i < TM; i++)
                #pragma unroll
                for (int j = 0; j < TN; j++)
                    acc[i][j] = fmaf(regM[i], regN[j], acc[i][j]);
        }
        __syncthreads();
    }

    // epilogue: bias + relu, vectorized stores
    #pragma unroll
    for (int i = 0; i < TM; i++) {
        const long long cRow = (long long)tileM * BM + tRow * TM + i;
        #pragma unroll
        for (int j = 0; j < TN; j += 4) {
            const int col = tileN * BN + tCol * TN + j;
            float4 v;
            v.x = fmaxf(acc[i][j + 0] + bias[col + 0], 0.f);
            v.y = fmaxf(acc[i][j + 1] + bias[col + 1], 0.f);
            v.z = fmaxf(acc[i][j + 2] + bias[col + 2], 0.f);
            v.w = fmaxf(acc[i][j + 3] + bias[col + 3], 0.f);
            *reinterpret_cast<float4*>(C + cRow * N + col) = v;
        }
    }
}

// ---------------- fused head: small GEMMs + softmax + argmax + regression ----------------
// one warp per row; reads Hc (K=1024, 7 cols), Ho (K=512, 6 cols), Hr (K=1024, 1 col)
__global__ void head_kernel(const float* __restrict__ Hc,
                            const float* __restrict__ Ho,
                            const float* __restrict__ Hr,
                            const float* __restrict__ Wc2, const float* __restrict__ bc2,
                            const float* __restrict__ Wo2, const float* __restrict__ bo2,
                            const float* __restrict__ Wr2, const float* __restrict__ br2,
                            float* __restrict__ out)
{
    const int row  = blockIdx.x * blockDim.y + threadIdx.y;
    if (row >= B_ROWS) return;
    const int lane = threadIdx.x;

    float a[7] = {0,0,0,0,0,0,0};
    {
        const float* h = Hc + (long long)row * D_DIM;
        for (int k = lane; k < D_DIM; k += 32) {
            const float hv = h[k];
            const float* w = Wc2 + k * 7;
            #pragma unroll
            for (int c = 0; c < 7; c++) a[c] = fmaf(hv, w[c], a[c]);
        }
    }
    float o[6] = {0,0,0,0,0,0};
    {
        const float* h = Ho + (long long)row * ORD_H;
        for (int k = lane; k < ORD_H; k += 32) {
            const float hv = h[k];
            const float* w = Wo2 + k * 6;
            #pragma unroll
            for (int c = 0; c < 6; c++) o[c] = fmaf(hv, w[c], o[c]);
        }
    }
    float r = 0.f;
    {
        const float* h = Hr + (long long)row * D_DIM;
        for (int k = lane; k < D_DIM; k += 32) r = fmaf(h[k], Wr2[k], r);
    }

    #pragma unroll
    for (int off = 16; off; off >>= 1) {
        #pragma unroll
        for (int c = 0; c < 7; c++) a[c] += __shfl_xor_sync(0xffffffffu, a[c], off);
        #pragma unroll
        for (int c = 0; c < 6; c++) o[c] += __shfl_xor_sync(0xffffffffu, o[c], off);
        r += __shfl_xor_sync(0xffffffffu, r, off);
    }

    if (lane == 0) {
        float sl[7];
        #pragma unroll
        for (int c = 0; c < 7; c++) sl[c] = a[c] + bc2[c];

        // softmax (max-subtracted)
        float mx = sl[0];
        #pragma unroll
        for (int c = 1; c < 7; c++) mx = fmaxf(mx, sl[c]);
        float ex[7], s = 0.f;
        #pragma unroll
        for (int c = 0; c < 7; c++) { ex[c] = expf(sl[c] - mx); s += ex[c]; }
        const float inv = 1.f / s;

        float expected = 0.f;
        int   idx  = 0;
        float best = sl[0];
        float* orow = out + (long long)row * 24;
        #pragma unroll
        for (int c = 0; c < 7; c++) {
            const float p = ex[c] * inv;
            expected = fmaf(p, (float)c * (1.0f / 6.0f), expected);
            orow[c]      = sl[c];   // size_logits
            orow[14 + c] = p;       // size_probs
            if (sl[c] > best) { best = sl[c]; idx = c; }   // first-max tie-break
        }
        #pragma unroll
        for (int c = 0; c < 6; c++) orow[7 + c] = o[c] + bo2[c];  // ord logits

        const float resid = 0.35f * tanhf(r + br2[0]);
        orow[13] = fminf(fmaxf(expected + resid, 0.f), 1.f);      // size_reg_norm
        d_size_idx[row] = idx;
    }
}

// ---------------- routing ----------------
__global__ void route_init_kernel()
{
    const int t = threadIdx.x;
    if (t < N_EXP) { d_count[t] = 0; d_cursor[t] = 0; d_off[t] = 0; }
    if (t < MAX_TILES) d_tile_expert[t] = -1;
}

__global__ void perm_init_kernel()
{
    const int i = blockIdx.x * blockDim.x + threadIdx.x;
    if (i < MAX_SLOTS) d_perm[i] = -1;
}

__global__ void count_kernel()
{
    const int r = blockIdx.x * blockDim.x + threadIdx.x;
    if (r < B_ROWS) atomicAdd(&d_count[d_size_idx[r]], 1);
}

__global__ void scan_kernel()
{
    // single thread: aligned exclusive scan + tile->expert map
    int off = 0;
    for (int e = 0; e < N_EXP; e++) {
        d_off[e] = off;
        const int tiles = (d_count[e] + 127) >> 7;
        const int base  = off >> 7;
        for (int t = 0; t < tiles; t++) d_tile_expert[base + t] = e;
        off += tiles << 7;
    }
}

__global__ void scatter_kernel()
{
    const int r = blockIdx.x * blockDim.x + threadIdx.x;
    if (r < B_ROWS) {
        const int e   = d_size_idx[r];
        const int pos = d_off[e] + atomicAdd(&d_cursor[e], 1);
        d_perm[pos] = r;
    }
}

// ---------------- final depth projection + scatter to output ----------------
// one warp per compact slot: dot h2[slot] with We3[e] (1024x3)
__global__ void depth_final_kernel(const float* __restrict__ H2,
                                   const float* __restrict__ We3,
                                   const float* __restrict__ be3,
                                   float* __restrict__ out)
{
    const int slot = blockIdx.x * blockDim.y + threadIdx.y;
    if (slot >= MAX_SLOTS) return;
    const int e = d_tile_expert[slot >> 7];
    if (e < 0) return;
    const int p = d_perm[slot];
    if (p < 0) return;

    const int lane = threadIdx.x;
    float a0 = 0.f, a1 = 0.f, a2 = 0.f;
    const float* h = H2 + (long long)slot * D_DIM;
    const float* w = We3 + (long long)e * D_DIM * 3;
    for (int k = lane; k < D_DIM; k += 32) {
        const float hv = h[k];
        a0 = fmaf(hv, w[k * 3 + 0], a0);
        a1 = fmaf(hv, w[k * 3 + 1], a1);
        a2 = fmaf(hv, w[k * 3 + 2], a2);
    }
    #pragma unroll
    for (int off = 16; off; off >>= 1) {
        a0 += __shfl_xor_sync(0xffffffffu, a0, off);
        a1 += __shfl_xor_sync(0xffffffffu, a1, off);
        a2 += __shfl_xor_sync(0xffffffffu, a2, off);
    }
    if (lane == 0) {
        float* orow = out + (long long)p * 24;
        orow[21] = a0 + be3[e * 3 + 0];
        orow[22] = a1 + be3[e * 3 + 1];
        orow[23] = a2 + be3[e * 3 + 2];
    }
}

// ---------------- launch ----------------
extern "C" void kernel_launch(void* const* d_in, const int* in_sizes, int n_in,
                              void* d_out, int out_size)
{
    const float* x   = (const float*)d_in[0];
    const float* Wc1 = (const float*)d_in[1];
    const float* bc1 = (const float*)d_in[2];
    const float* Wc2 = (const float*)d_in[3];
    const float* bc2 = (const float*)d_in[4];
    const float* Wo1 = (const float*)d_in[5];
    const float* bo1 = (const float*)d_in[6];
    const float* Wo2 = (const float*)d_in[7];
    const float* bo2 = (const float*)d_in[8];
    const float* Wr1 = (const float*)d_in[9];
    const float* br1 = (const float*)d_in[10];
    const float* Wr2 = (const float*)d_in[11];
    const float* br2 = (const float*)d_in[12];
    const float* Wa  = (const float*)d_in[13];
    const float* ba  = (const float*)d_in[14];
    const float* We1 = (const float*)d_in[15];
    const float* be1 = (const float*)d_in[16];
    const float* We2 = (const float*)d_in[17];
    const float* be2 = (const float*)d_in[18];
    const float* We3 = (const float*)d_in[19];
    const float* be3 = (const float*)d_in[20];
    float* out = (float*)d_out;

    float* buf = nullptr;
    cudaGetSymbolAddress((void**)&buf, g_buf);   // host-side, capture-safe
    float* Hc = buf + OFF_HC;
    float* Hr = buf + OFF_HR;
    float* Df = buf + OFF_DF;
    float* Ho = buf + OFF_HO;
    float* H1 = buf + OFF_H1;
    float* H2 = buf + OFF_H2;

    const int mTiles = B_ROWS / BM;  // 128

    // stage 1: four first-layer GEMMs (bias + relu)
    sgemm_relu<<<dim3(mTiles, D_DIM / BN), 256>>>(x, Wc1, bc1, Hc, D_DIM, D_DIM, 0, 0, 0, 0);
    sgemm_relu<<<dim3(mTiles, D_DIM / BN), 256>>>(x, Wr1, br1, Hr, D_DIM, D_DIM, 0, 0, 0, 0);
    sgemm_relu<<<dim3(mTiles, D_DIM / BN), 256>>>(x, Wa,  ba,  Df, D_DIM, D_DIM, 0, 0, 0, 0);
    sgemm_relu<<<dim3(mTiles, ORD_H / BN), 256>>>(x, Wo1, bo1, Ho, D_DIM, ORD_H, 0, 0, 0, 0);

    // stage 2: fused heads (size logits/probs/ord/regression) + routing decision
    head_kernel<<<B_ROWS / 8, dim3(32, 8)>>>(Hc, Ho, Hr, Wc2, bc2, Wo2, bo2, Wr2, br2, out);

    // stage 3: build compact per-expert dispatch
    route_init_kernel<<<1, 256>>>();
    perm_init_kernel<<<(MAX_SLOTS + 255) / 256, 256>>>();
    count_kernel<<<(B_ROWS + 255) / 256, 256>>>();
    scan_kernel<<<1, 1>>>();
    scatter_kernel<<<(B_ROWS + 255) / 256, 256>>>();

    // stage 4: routed expert MLP (each row computed for exactly ONE expert)
    sgemm_relu<<<dim3(MAX_TILES, D_DIM / BN), 256>>>(Df, We1, be1, H1, D_DIM, D_DIM, 1, 1,
                                                     (long long)D_DIM * D_DIM, D_DIM);
    sgemm_relu<<<dim3(MAX_TILES, D_DIM / BN), 256>>>(H1, We2, be2, H2, D_DIM, D_DIM, 1, 0,
                                                     (long long)D_DIM * D_DIM, D_DIM);

    // stage 5: 1024x3 projection + scatter depth logits to output rows
    depth_final_kernel<<<MAX_SLOTS / 8, dim3(32, 8)>>>(H2, We3, be3, out);
}